// round 12
// baseline (speedup 1.0000x reference)
#include <cuda_runtime.h>
#include <math.h>

// Problem constants (from reference)
#define L_A        128
#define B_DIM      64
#define NUM_PAIRS  (L_A * B_DIM)   // 8192
#define NUM_RULES  256
#define NUM_TOKENS 32000
#define MAX_QUERY  512
#define EPS_VAL    1e-7f

#define BLOCKS   256
#define THREADS  32    // warp-sized blocks: no __syncthreads, no shared memory

__device__ float g_partials[BLOCKS];

__device__ __forceinline__ float gather_or_zero(const float* __restrict__ p,
                                                int pair, int stride, int idx) {
    // idx == -1 contributes 0 (matches reference _gather_prob)
    int safe = idx < 0 ? 0 : idx;
    float v = __ldg(p + (long long)pair * stride + safe);
    return (idx == -1) ? 0.0f : v;
}

__device__ __forceinline__ float warp_reduce(float v) {
    #pragma unroll
    for (int off = 16; off > 0; off >>= 1)
        v += __shfl_xor_sync(0xFFFFFFFFu, v, off);
    return v;
}

__global__ void __launch_bounds__(THREADS)
loss_gather_kernel(const float* __restrict__ rule_prob,
                   const float* __restrict__ token_prob,
                   const float* __restrict__ copy_prob,
                   const int*   __restrict__ gt_rule,
                   const int*   __restrict__ gt_token,
                   const int*   __restrict__ gt_copy,
                   const float* __restrict__ mask) {
    // PDL: allow the dependent (final) kernel to begin its launch now; its
    // griddepcontrol.wait still gates on this grid's full memory flush.
    asm volatile("griddepcontrol.launch_dependents;" ::: "memory");

    int pair = blockIdx.x * THREADS + threadIdx.x;   // 0..8191

    // Indices first (independent), then all 3 gathers (independent -> MLP >= 3)
    int r = gt_rule[pair];
    int t = gt_token[pair];
    int c = gt_copy[pair];
    float m = mask[pair];

    float prob = gather_or_zero(rule_prob,  pair, NUM_RULES,  r)
               + gather_or_zero(token_prob, pair, NUM_TOKENS, t)
               + gather_or_zero(copy_prob,  pair, MAX_QUERY,  c);

    // reference: prob = prob + (prob < EPS) * EPS   (an add, not a clamp)
    if (prob < EPS_VAL) prob += EPS_VAL;

    // __logf: MUFU.LG2 * ln2 — rel err ~2^-21 vs 1e-3 tolerance.
    float loss = -__logf(prob) * m;

    // warp-level reduce only — no barrier, no shared memory
    loss = warp_reduce(loss);
    if (threadIdx.x == 0)
        g_partials[blockIdx.x] = loss;
}

__global__ void loss_final_kernel(float* __restrict__ out) {
    // PDL: wait until the primary grid's memory writes are visible.
    asm volatile("griddepcontrol.wait;" ::: "memory");

    int lane = threadIdx.x;   // 32 threads; 256 partials -> 2 float4 per lane
    const float4* p4 = (const float4*)g_partials;
    float4 a = p4[lane];           // independent LDG.128 x2 -> one L2 round trip
    float4 b = p4[lane + 32];
    float v = ((a.x + a.y) + (a.z + a.w)) + ((b.x + b.y) + (b.z + b.w));
    v = warp_reduce(v);
    if (lane == 0) out[0] = v * (1.0f / (float)B_DIM);
}

extern "C" void kernel_launch(void* const* d_in, const int* in_sizes, int n_in,
                              void* d_out, int out_size) {
    const float* rule_prob  = (const float*)d_in[0];
    const float* token_prob = (const float*)d_in[1];
    const float* copy_prob  = (const float*)d_in[2];
    const int*   gt_rule    = (const int*)  d_in[3];
    const int*   gt_token   = (const int*)  d_in[4];
    const int*   gt_copy    = (const int*)  d_in[5];
    const float* mask       = (const float*)d_in[6];
    float* out = (float*)d_out;

    loss_gather_kernel<<<BLOCKS, THREADS>>>(rule_prob, token_prob, copy_prob,
                                            gt_rule, gt_token, gt_copy, mask);

    // Final reduction with Programmatic Dependent Launch: its launch latency
    // overlaps the gather kernel's execution.
    cudaLaunchAttribute attrs[1];
    attrs[0].id = cudaLaunchAttributeProgrammaticStreamSerialization;
    attrs[0].val.programmaticStreamSerializationAllowed = 1;

    cudaLaunchConfig_t cfg = {};
    cfg.gridDim  = dim3(1, 1, 1);
    cfg.blockDim = dim3(32, 1, 1);
    cfg.dynamicSmemBytes = 0;
    cfg.stream = 0;           // legacy default stream (the one the harness captures)
    cfg.attrs = attrs;
    cfg.numAttrs = 1;

    cudaError_t err = cudaLaunchKernelEx(&cfg, loss_final_kernel, out);
    if (err != cudaSuccess) {
        cudaGetLastError();
        // Fallback: plain serialized launch (still correct, no PDL overlap).
        loss_final_kernel<<<1, 32>>>(out);
    }
}

// round 13
// speedup vs baseline: 1.0337x; 1.0337x over previous
#include <cuda_runtime.h>
#include <math.h>

// Problem constants (from reference)
#define L_A        128
#define B_DIM      64
#define NUM_PAIRS  (L_A * B_DIM)   // 8192
#define NUM_RULES  256
#define NUM_TOKENS 32000
#define MAX_QUERY  512
#define EPS_VAL    1e-7f

#define BLOCKS   64
#define THREADS  128   // BLOCKS * THREADS == NUM_PAIRS; single wave (64 < 148 SMs)

__device__ float g_partials[BLOCKS];

__device__ __forceinline__ float gather_or_zero(const float* __restrict__ p,
                                                int pair, int stride, int idx) {
    // idx == -1 contributes 0 (matches reference _gather_prob)
    int safe = idx < 0 ? 0 : idx;
    float v = __ldg(p + (long long)pair * stride + safe);
    return (idx == -1) ? 0.0f : v;
}

__device__ __forceinline__ float warp_reduce(float v) {
    #pragma unroll
    for (int off = 16; off > 0; off >>= 1)
        v += __shfl_xor_sync(0xFFFFFFFFu, v, off);
    return v;
}

__global__ void __launch_bounds__(THREADS, 1)
loss_gather_kernel(const float* __restrict__ rule_prob,
                   const float* __restrict__ token_prob,
                   const float* __restrict__ copy_prob,
                   const int*   __restrict__ gt_rule,
                   const int*   __restrict__ gt_token,
                   const int*   __restrict__ gt_copy,
                   const float* __restrict__ mask) {
    // PDL: allow the dependent (final) kernel to begin its launch now; its
    // griddepcontrol.wait still gates on this grid's full memory flush.
    asm volatile("griddepcontrol.launch_dependents;" ::: "memory");

    int pair = blockIdx.x * blockDim.x + threadIdx.x;   // 0..8191

    // Indices first (independent), then all 3 gathers (independent -> MLP >= 3)
    int r = gt_rule[pair];
    int t = gt_token[pair];
    int c = gt_copy[pair];
    float m = mask[pair];

    float prob = gather_or_zero(rule_prob,  pair, NUM_RULES,  r)
               + gather_or_zero(token_prob, pair, NUM_TOKENS, t)
               + gather_or_zero(copy_prob,  pair, MAX_QUERY,  c);

    // reference: prob = prob + (prob < EPS) * EPS   (an add, not a clamp)
    if (prob < EPS_VAL) prob += EPS_VAL;

    // __logf: MUFU.LG2 * ln2 — rel err ~2^-21 vs 1e-3 tolerance.
    // prob is in (EPS, 3): well-conditioned for the fast path.
    float loss = -__logf(prob) * m;

    // --- block reduction: warp shuffle, then 4-warp combine via shared ---
    loss = warp_reduce(loss);

    __shared__ float warp_sums[THREADS / 32];   // 4
    int lane = threadIdx.x & 31;
    int wid  = threadIdx.x >> 5;
    if (lane == 0) warp_sums[wid] = loss;
    __syncthreads();

    if (threadIdx.x == 0)
        g_partials[blockIdx.x] = (warp_sums[0] + warp_sums[1])
                               + (warp_sums[2] + warp_sums[3]);
}

__global__ void loss_final_kernel(float* __restrict__ out) {
    // PDL: wait until the primary grid's memory writes are visible.
    asm volatile("griddepcontrol.wait;" ::: "memory");

    int lane = threadIdx.x;   // 32 threads; 64 partials -> one float2 per lane
    float2 p = *((const float2*)g_partials + lane);
    float v = p.x + p.y;
    v = warp_reduce(v);
    if (lane == 0) out[0] = v * (1.0f / (float)B_DIM);
}

extern "C" void kernel_launch(void* const* d_in, const int* in_sizes, int n_in,
                              void* d_out, int out_size) {
    const float* rule_prob  = (const float*)d_in[0];
    const float* token_prob = (const float*)d_in[1];
    const float* copy_prob  = (const float*)d_in[2];
    const int*   gt_rule    = (const int*)  d_in[3];
    const int*   gt_token   = (const int*)  d_in[4];
    const int*   gt_copy    = (const int*)  d_in[5];
    const float* mask       = (const float*)d_in[6];
    float* out = (float*)d_out;

    loss_gather_kernel<<<BLOCKS, THREADS>>>(rule_prob, token_prob, copy_prob,
                                            gt_rule, gt_token, gt_copy, mask);

    // Final reduction with Programmatic Dependent Launch: its launch latency
    // overlaps the gather kernel's execution.
    cudaLaunchAttribute attrs[1];
    attrs[0].id = cudaLaunchAttributeProgrammaticStreamSerialization;
    attrs[0].val.programmaticStreamSerializationAllowed = 1;

    cudaLaunchConfig_t cfg = {};
    cfg.gridDim  = dim3(1, 1, 1);
    cfg.blockDim = dim3(32, 1, 1);
    cfg.dynamicSmemBytes = 0;
    cfg.stream = 0;           // legacy default stream (the one the harness captures)
    cfg.attrs = attrs;
    cfg.numAttrs = 1;

    cudaError_t err = cudaLaunchKernelEx(&cfg, loss_final_kernel, out);
    if (err != cudaSuccess) {
        cudaGetLastError();
        // Fallback: plain serialized launch (still correct, no PDL overlap).
        loss_final_kernel<<<1, 32>>>(out);
    }
}

// round 16
// speedup vs baseline: 1.0386x; 1.0048x over previous
#include <cuda_runtime.h>
#include <math.h>

// Problem constants (from reference)
#define L_A        128
#define B_DIM      64
#define NUM_PAIRS  (L_A * B_DIM)   // 8192
#define NUM_RULES  256
#define NUM_TOKENS 32000
#define MAX_QUERY  512
#define EPS_VAL    1e-7f

#define BLOCKS   64
#define THREADS  128   // BLOCKS * THREADS == NUM_PAIRS; single wave (64 < 148 SMs)

__device__ float g_partials[BLOCKS];

__device__ __forceinline__ float gather_or_zero(const float* __restrict__ p,
                                                int pair, int stride, int idx) {
    // idx == -1 contributes 0 (matches reference _gather_prob)
    int safe = idx < 0 ? 0 : idx;
    float v = __ldg(p + (long long)pair * stride + safe);
    return (idx == -1) ? 0.0f : v;
}

__device__ __forceinline__ float warp_reduce(float v) {
    #pragma unroll
    for (int off = 16; off > 0; off >>= 1)
        v += __shfl_xor_sync(0xFFFFFFFFu, v, off);
    return v;
}

__global__ void __launch_bounds__(THREADS, 1)
loss_gather_kernel(const float* __restrict__ rule_prob,
                   const float* __restrict__ token_prob,
                   const float* __restrict__ copy_prob,
                   const int*   __restrict__ gt_rule,
                   const int*   __restrict__ gt_token,
                   const int*   __restrict__ gt_copy,
                   const float* __restrict__ mask) {
    // PDL: allow the dependent (final) kernel to begin its launch now; its
    // griddepcontrol.wait still gates on this grid's full memory flush.
    asm volatile("griddepcontrol.launch_dependents;" ::: "memory");

    int pair = blockIdx.x * blockDim.x + threadIdx.x;   // 0..8191

    // Indices first (independent), then all 3 gathers (independent -> MLP >= 3)
    int r = gt_rule[pair];
    int t = gt_token[pair];
    int c = gt_copy[pair];
    float m = mask[pair];

    float prob = gather_or_zero(rule_prob,  pair, NUM_RULES,  r)
               + gather_or_zero(token_prob, pair, NUM_TOKENS, t)
               + gather_or_zero(copy_prob,  pair, MAX_QUERY,  c);

    // reference: prob = prob + (prob < EPS) * EPS   (an add, not a clamp)
    if (prob < EPS_VAL) prob += EPS_VAL;

    // __logf: MUFU.LG2 * ln2 — rel err ~2^-21 vs 1e-3 tolerance.
    // prob is in (EPS, 3): well-conditioned for the fast path.
    float loss = -__logf(prob) * m;

    // --- block reduction: warp shuffle, then 4-warp combine via shared ---
    loss = warp_reduce(loss);

    __shared__ float warp_sums[THREADS / 32];   // 4
    int lane = threadIdx.x & 31;
    int wid  = threadIdx.x >> 5;
    if (lane == 0) warp_sums[wid] = loss;
    __syncthreads();

    if (threadIdx.x == 0)
        g_partials[blockIdx.x] = (warp_sums[0] + warp_sums[1])
                               + (warp_sums[2] + warp_sums[3]);
}

__global__ void loss_final_kernel(float* __restrict__ out) {
    // PDL: wait until the primary grid's memory writes are visible.
    asm volatile("griddepcontrol.wait;" ::: "memory");

    int lane = threadIdx.x;   // 32 threads; 64 partials -> one float2 per lane
    float2 p = *((const float2*)g_partials + lane);
    float v = p.x + p.y;
    v = warp_reduce(v);
    if (lane == 0) out[0] = v * (1.0f / (float)B_DIM);
}

extern "C" void kernel_launch(void* const* d_in, const int* in_sizes, int n_in,
                              void* d_out, int out_size) {
    const float* rule_prob  = (const float*)d_in[0];
    const float* token_prob = (const float*)d_in[1];
    const float* copy_prob  = (const float*)d_in[2];
    const int*   gt_rule    = (const int*)  d_in[3];
    const int*   gt_token   = (const int*)  d_in[4];
    const int*   gt_copy    = (const int*)  d_in[5];
    const float* mask       = (const float*)d_in[6];
    float* out = (float*)d_out;

    loss_gather_kernel<<<BLOCKS, THREADS>>>(rule_prob, token_prob, copy_prob,
                                            gt_rule, gt_token, gt_copy, mask);

    // Final reduction with Programmatic Dependent Launch: its launch latency
    // overlaps the gather kernel's execution.
    cudaLaunchAttribute attrs[1];
    attrs[0].id = cudaLaunchAttributeProgrammaticStreamSerialization;
    attrs[0].val.programmaticStreamSerializationAllowed = 1;

    cudaLaunchConfig_t cfg = {};
    cfg.gridDim  = dim3(1, 1, 1);
    cfg.blockDim = dim3(32, 1, 1);
    cfg.dynamicSmemBytes = 0;
    cfg.stream = 0;           // legacy default stream (the one the harness captures)
    cfg.attrs = attrs;
    cfg.numAttrs = 1;

    cudaError_t err = cudaLaunchKernelEx(&cfg, loss_final_kernel, out);
    if (err != cudaSuccess) {
        cudaGetLastError();
        // Fallback: plain serialized launch (still correct, no PDL overlap).
        loss_final_kernel<<<1, 32>>>(out);
    }
}